// round 11
// baseline (speedup 1.0000x reference)
#include <cuda_runtime.h>

// TransientCombNoise: B=32, T=2000, BLOCK=64, SR=16000, MAX_DELAY=480
// N = 64000 independent rows of 64 samples.
//
//   delay = int(32 + 32*bandwidth) in [33, 63]  =>  single FIR tap:
//       y[s] = x[s] + (s >= delay ? tilt * x[s-delay] : 0)
//   envelope exp(-s/a) = r^s via binary decomposition (1 expf per ROW).
//   out = y * rsqrt(mean(y^2) + 1e-5)
//
// Latency/MIO-bound => cut SHFL count and chain length:
//   - params for 8 rows computed once per warp, 4 scalars broadcast per row
//     (r32 derived locally from r: one extra FMUL instead of a 5th shfl).
//   - PAIRED reduce: two rows share one butterfly. After one xor-1 step per
//     row, a parity select merges them; masks 2/4/8/16 preserve parity so the
//     4-step chain reduces both rows at once; one xor-1 + 2 selects recover
//     both sums in every lane. 7 shfls / 2 rows instead of 10.
//   - 128-thread blocks for better SM load balance (2000 blocks).

#define N_ROWS (32 * 2000)
#define BATCH  8
#define NWARPS (N_ROWS / BATCH)   // 8000

__global__ void __launch_bounds__(128)
transient_comb_kernel(const float4* __restrict__ params4, // [N] float4
                      const float*  __restrict__ noise,   // [N,64]
                      float*        __restrict__ out)     // [N,64]
{
    const int warp = (blockIdx.x * blockDim.x + threadIdx.x) >> 5;
    const int lane = threadIdx.x & 31;
    if (warp >= NWARPS) return;

    const int base = warp * BATCH;

    // ---- prologue: per-lane params for row base + (lane&7) ----
    const float4 p = params4[base + (lane & 7)];

    const float energy = p.y;
    const float tilt   = p.z * 2.0f - 1.0f;

    // Replicate XLA's separate-op fp32 rounding at the int-trunc boundary:
    const float bandwidth = __fadd_rn(0.05f, __fmul_rn(p.w, 0.95f));
    const float dval      = __fmul_rn(64.0f,
                              __fadd_rn(0.5f, __fmul_rn(0.5f, bandwidth)));
    int delay = (int)dval;
    delay = min(max(delay, 1), 480);

    const float attack_samples =
        fmaxf((0.0005f + p.x * 0.0495f) * 16000.0f, 1.0f);
    const float r = __expf(-1.0f / attack_samples);

    // loop-invariant lane predicates for the power decomposition
    const bool l1  = (lane & 1)  != 0;
    const bool l2  = (lane & 2)  != 0;
    const bool l4  = (lane & 4)  != 0;
    const bool l8  = (lane & 8)  != 0;
    const bool l16 = (lane & 16) != 0;
    const bool lodd = l1;

    const float* __restrict__ nrow = noise + (size_t)base * 64 + lane;
    float*       __restrict__ orow = out   + (size_t)base * 64 + lane;

    #pragma unroll
    for (int jp = 0; jp < BATCH; jp += 2) {
        const int jA = jp, jB = jp + 1;

        // ---- broadcast 4 scalars per row (8 shfls / 2 rows) ----
        const float rA = __shfl_sync(0xffffffffu, r,      jA);
        const float rB = __shfl_sync(0xffffffffu, r,      jB);
        const float eA = __shfl_sync(0xffffffffu, energy, jA);
        const float eB = __shfl_sync(0xffffffffu, energy, jB);
        const float tA = __shfl_sync(0xffffffffu, tilt,   jA);
        const float tB = __shfl_sync(0xffffffffu, tilt,   jB);
        const int   dA = __shfl_sync(0xffffffffu, delay,  jA);
        const int   dB = __shfl_sync(0xffffffffu, delay,  jB);

        // ---- loads (4 coalesced LDGs, independent of all math above) ----
        const float xA0 = nrow[jA * 64];
        const float xA1 = nrow[jA * 64 + 32];
        const float xB0 = nrow[jB * 64];
        const float xB1 = nrow[jB * 64 + 32];

        // ---- envelopes: e = energy * r^lane, r32 derived locally ----
        const float qA2 = rA * rA,  qA4 = qA2 * qA2;
        const float qA8 = qA4 * qA4, qA16 = qA8 * qA8, qA32 = qA16 * qA16;
        float envA = eA;
        if (l1)  envA *= rA;
        if (l2)  envA *= qA2;
        if (l4)  envA *= qA4;
        if (l8)  envA *= qA8;
        if (l16) envA *= qA16;
        const float envA1 = envA * qA32;

        const float qB2 = rB * rB,  qB4 = qB2 * qB2;
        const float qB8 = qB4 * qB4, qB16 = qB8 * qB8, qB32 = qB16 * qB16;
        float envB = eB;
        if (l1)  envB *= rB;
        if (l2)  envB *= qB2;
        if (l4)  envB *= qB4;
        if (l8)  envB *= qB8;
        if (l16) envB *= qB16;
        const float envB1 = envB * qB32;

        const float bA0 = xA0 * envA;
        const float bA1 = xA1 * envA1;
        const float bB0 = xB0 * envB;
        const float bB1 = xB1 * envB1;

        // ---- comb tap (1 shfl per row); delay in [33,63] => only high half,
        //      source is always the LOW sample (b*0) of lane s-delay < 32.
        const int   idxA = lane + 32 - dA;
        const float srcA = __shfl_sync(0xffffffffu, bA0, idxA & 31);
        const float yA1  = bA1 + ((idxA >= 0) ? tA * srcA : 0.0f);

        const int   idxB = lane + 32 - dB;
        const float srcB = __shfl_sync(0xffffffffu, bB0, idxB & 31);
        const float yB1  = bB1 + ((idxB >= 0) ? tB * srcB : 0.0f);

        // ---- paired reduce: 7 shfls for both rows ----
        float u = fmaf(bA0, bA0, yA1 * yA1);
        float v = fmaf(bB0, bB0, yB1 * yB1);
        u += __shfl_xor_sync(0xffffffffu, u, 1);
        v += __shfl_xor_sync(0xffffffffu, v, 1);
        float c = lodd ? v : u;          // even lanes carry A, odd carry B
        c += __shfl_xor_sync(0xffffffffu, c, 2);
        c += __shfl_xor_sync(0xffffffffu, c, 4);
        c += __shfl_xor_sync(0xffffffffu, c, 8);
        c += __shfl_xor_sync(0xffffffffu, c, 16);
        const float cx  = __shfl_xor_sync(0xffffffffu, c, 1);
        const float ssA = lodd ? cx : c;
        const float ssB = lodd ? c  : cx;

        const float invA = rsqrtf(fmaf(ssA, (1.0f / 64.0f), 1e-5f));
        const float invB = rsqrtf(fmaf(ssB, (1.0f / 64.0f), 1e-5f));

        orow[jA * 64]      = bA0 * invA;
        orow[jA * 64 + 32] = yA1 * invA;
        orow[jB * 64]      = bB0 * invB;
        orow[jB * 64 + 32] = yB1 * invB;
    }
}

extern "C" void kernel_launch(void* const* d_in, const int* in_sizes, int n_in,
                              void* d_out, int out_size)
{
    const float4* params = (const float4*)d_in[0];  // [32,2000,4]
    const float*  noise  = (const float*)d_in[1];   // [32,2000,64]
    float* out           = (float*)d_out;           // [32, 2000*64]

    (void)in_sizes; (void)n_in; (void)out_size;

    // 8000 warps, one 8-row batch each: 2000 blocks x 128 threads
    const int threads = 128;
    const int blocks  = (NWARPS * 32) / threads;    // 2000
    transient_comb_kernel<<<blocks, threads>>>(params, noise, out);
}

// round 13
// speedup vs baseline: 1.2179x; 1.2179x over previous
#include <cuda_runtime.h>

// TransientCombNoise: B=32, T=2000, BLOCK=64, SR=16000, MAX_DELAY=480
// N = 64000 independent rows of 64 samples.
//
//   delay = int(32 + 32*bandwidth) in [33, 63]  =>  single FIR tap:
//       y[s] = x[s] + (s >= delay ? tilt * x[s-delay] : 0)
//   envelope exp(-s/a) = r^s via binary decomposition (1 expf per ROW).
//   out = y * rsqrt(mean(y^2) + 1e-5)
//
// Layout: HALF-WARP per row, 4 samples per lane (float4):
//   - 1 LDG.128 + 1 STG.128 per 2 rows (was 4+4 scalar).
//   - RMS reduce = 4 shfl_xor (masks 1..8 stay inside each 16-lane half;
//     both rows reduce in the same chain, no merge selects).
//   - tap: source component (k-delay)&3 is uniform per half -> 3 SELs +
//     one width-16 shfl per k (4 tap shfls / 2 rows).
//   - params for 8 rows computed once per warp; per-half broadcast shfl
//     (src = 2u + h) gives each half its own row's scalars.
//   6 shfls/row total (was 11), inter-iteration ILP preserved.

#define N_ROWS (32 * 2000)
#define BATCH  8                  // rows per warp
#define NWARPS (N_ROWS / BATCH)   // 8000
#define FULLM  0xffffffffu

__global__ void __launch_bounds__(256)
transient_comb_kernel(const float4* __restrict__ params4, // [N] float4
                      const float4* __restrict__ noise4,  // [N*16] float4
                      float4*       __restrict__ out4)    // [N*16] float4
{
    const int warp = (blockIdx.x * blockDim.x + threadIdx.x) >> 5;
    const int lane = threadIdx.x & 31;
    if (warp >= NWARPS) return;

    const int base = warp * BATCH;
    const int h    = lane >> 4;       // half: 0 -> even row, 1 -> odd row
    const int hl   = lane & 15;       // sub-lane within half
    const int s0   = hl << 2;         // first sample index handled (0..60)

    // ---- prologue: per-lane params for row base + (lane&7) ----
    const float4 p = params4[base + (lane & 7)];

    const float energy = p.y;
    const float tilt   = p.z * 2.0f - 1.0f;

    // Replicate XLA's separate-op fp32 rounding at the int-trunc boundary:
    const float bandwidth = __fadd_rn(0.05f, __fmul_rn(p.w, 0.95f));
    const float dval      = __fmul_rn(64.0f,
                              __fadd_rn(0.5f, __fmul_rn(0.5f, bandwidth)));
    int delay = (int)dval;
    delay = min(max(delay, 1), 480);

    const float attack_samples =
        fmaxf((0.0005f + p.x * 0.0495f) * 16000.0f, 1.0f);
    const float r = __expf(-1.0f / attack_samples);

    // loop-invariant predicates for the r^(4*hl) decomposition
    const bool g1 = (hl & 1) != 0;
    const bool g2 = (hl & 2) != 0;
    const bool g4 = (hl & 4) != 0;
    const bool g8 = (hl & 8) != 0;

    // float4 base: row*16 + hl  ->  (base + 2u + h)*16 + hl = base*16 + 32u + lane
    const float4* __restrict__ nvec = noise4 + (size_t)base * 16 + lane;
    float4*       __restrict__ ovec = out4   + (size_t)base * 16 + lane;

    #pragma unroll
    for (int u = 0; u < BATCH / 2; u++) {
        // ---- per-half broadcast of this pair's scalars (4 shfls / 2 rows) ----
        const int   srcp = 2 * u + h;
        const float rj = __shfl_sync(FULLM, r,      srcp);
        const float ej = __shfl_sync(FULLM, energy, srcp);
        const float tj = __shfl_sync(FULLM, tilt,   srcp);
        const int   dj = __shfl_sync(FULLM, delay,  srcp);

        // ---- one vector load per 2 rows ----
        const float4 x = nvec[32 * u];

        // ---- envelope: env = energy * r^(4*hl), then * r^k ----
        const float r2 = rj * rj;
        const float r4 = r2 * r2;     // r^4  (bit 0 of hl)
        const float s2 = r4 * r4;     // r^8  (bit 1)
        const float s4 = s2 * s2;     // r^16 (bit 2)
        const float s8 = s4 * s4;     // r^32 (bit 3)
        float env = ej;
        if (g1) env *= r4;
        if (g2) env *= s2;
        if (g4) env *= s4;
        if (g8) env *= s8;            // env = energy * r^(4*hl)
        const float e1 = env * rj;
        const float e2 = e1  * rj;
        const float e3 = e2  * rj;

        const float b0 = x.x * env;
        const float b1 = x.y * e1;
        const float b2 = x.z * e2;
        const float b3 = x.w * e3;

        // ---- comb tap: sample s=s0+k taps sample s-dj (always a pre-tap
        //      burst value, since s-dj <= 30 < dj). comp=(k-dj)&3 uniform/half.
        float y0 = b0, y1 = b1, y2 = b2, y3 = b3;
        #pragma unroll
        for (int k = 0; k < 4; k++) {
            const int   idx  = s0 + k - dj;              // [-63, 30]
            const int   sl   = (idx >> 2) & 15;          // source sub-lane
            const int   comp = (k - dj) & 3;             // uniform per half
            const float lo   = (comp & 1) ? b1 : b0;
            const float hi   = (comp & 1) ? b3 : b2;
            const float vk   = (comp & 2) ? hi : lo;     // own b[comp]
            const float src  = __shfl_sync(FULLM, vk, sl, 16);
            const float tap  = (idx >= 0) ? tj * src : 0.0f;
            if (k == 0) y0 = b0 + tap;
            if (k == 1) y1 = b1 + tap;
            if (k == 2) y2 = b2 + tap;
            if (k == 3) y3 = b3 + tap;
        }

        // ---- RMS: 16-lane butterfly (4 shfls serve BOTH rows) ----
        float ss = fmaf(y0, y0, y1 * y1) + fmaf(y2, y2, y3 * y3);
        ss += __shfl_xor_sync(FULLM, ss, 1);
        ss += __shfl_xor_sync(FULLM, ss, 2);
        ss += __shfl_xor_sync(FULLM, ss, 4);
        ss += __shfl_xor_sync(FULLM, ss, 8);

        const float inv = rsqrtf(fmaf(ss, (1.0f / 64.0f), 1e-5f));

        ovec[32 * u] = make_float4(y0 * inv, y1 * inv, y2 * inv, y3 * inv);
    }
}

extern "C" void kernel_launch(void* const* d_in, const int* in_sizes, int n_in,
                              void* d_out, int out_size)
{
    const float4* params = (const float4*)d_in[0];  // [32,2000,4]
    const float4* noise  = (const float4*)d_in[1];  // [32,2000,64] as float4
    float4* out          = (float4*)d_out;          // [32, 2000*64] as float4

    (void)in_sizes; (void)n_in; (void)out_size;

    // 8000 warps, 8 rows each: 1000 blocks x 256 threads
    const int threads = 256;
    const int blocks  = (NWARPS * 32) / threads;    // 1000
    transient_comb_kernel<<<blocks, threads>>>(params, noise, out);
}